// round 16
// baseline (speedup 1.0000x reference)
#include <cuda_runtime.h>
#include <cuda_fp16.h>
#include <math.h>
#include <stdint.h>

// ---------------------------------------------------------------------------
// 2-layer LSTM, T=512, B=64, H=512, fp32 in/out. Persistent, 128 CTAs x 512.
// R15 (base R14): HIERARCHICAL grid barrier. The flat ticket barrier cost
// ~3.5k cyc/step (128 atomics serialize ~27cyc each on ONE L2 address, per
// B300 L2-atom model). New: 8 leaf counters (256B apart, parallel slices,
// 16 arrivals each) -> root counter (8) -> release flag; waiters snapshot
// flag pre-arrival and acquire-poll for the bump. acq_rel chain preserves
// h-state visibility. Everything else unchanged from R14:
//   A (warps 0-7):  h0.Wx1 x2, h1.Wh1 x2 -> GB1 -> update h1(t)+out
//   B (warps 8-15): x.Wx0 x2, h0.Wh0 x2 -> GB0 -> update h0(t+1)
// single-term fp16 weights in regs, MUFU activations, x/GB alias,
// 3-slot h rotation, 1 grid bar/step.
// ---------------------------------------------------------------------------

#define T_LEN 512
#define BSZ   64
#define HID   512
#define NCTA  128
#define NTHR  512

// smem byte layout
#define CHUNKB  33280u
#define HB(i)   ((uint32_t)(i)*CHUNKB)     // h0 pair @0, @33280
#define H1P     (2u*CHUNKB)                // 66560: h1 pair (2 chunks)
#define XB0     (4u*CHUNKB)                // 133120 (aliases GB0/GB1)
#define XB1     (5u*CHUNKB)                // 166400
#define GB0F    33280u                     // float idx (byte 133120) [8][16][68]
#define GB1F    41984u                     // float idx (byte 167936) [8][16][68]
#define BSF     50688u                     // float idx (byte 202752)
#define SMEM_BYTES (202752u + 128u)        // 202880

// persistent scratch (fp16 activations)
__device__ __half g_xh[(size_t)T_LEN*BSZ*HID];
__device__ __half g_h0h[3][BSZ*HID];
__device__ __half g_h1h[3][BSZ*HID];
// hierarchical barrier state (all monotonic; replay-safe)
__device__ unsigned g_leaf[8 * 64];        // 8 counters, 256B apart
__device__ unsigned g_root;
__device__ unsigned g_flag;

__device__ __forceinline__ float fsigm(float x) {
    return __fdividef(1.0f, 1.0f + __expf(-x));
}
__device__ __forceinline__ float ftanh(float x) {
    float r;
    asm("tanh.approx.f32 %0, %1;" : "=f"(r) : "f"(x));
    return r;
}

__device__ __forceinline__ void cp16s(uint32_t dst, const void* src) {
    asm volatile("cp.async.cg.shared.global [%0], [%1], 16;" :: "r"(dst), "l"(src));
}
__device__ __forceinline__ void ldsm_x4(uint32_t addr, uint32_t r[4]) {
    asm volatile("ldmatrix.sync.aligned.m8n8.x4.shared.b16 {%0,%1,%2,%3}, [%4];"
        : "=r"(r[0]), "=r"(r[1]), "=r"(r[2]), "=r"(r[3]) : "r"(addr));
}
__device__ __forceinline__ void mma16816(float d[4], const uint32_t a[4],
                                         const uint32_t b[2]) {
    asm volatile("mma.sync.aligned.m16n8k16.row.col.f32.f16.f16.f32 "
        "{%0,%1,%2,%3}, {%4,%5,%6,%7}, {%8,%9}, {%0,%1,%2,%3};"
        : "+f"(d[0]), "+f"(d[1]), "+f"(d[2]), "+f"(d[3])
        : "r"(a[0]), "r"(a[1]), "r"(a[2]), "r"(a[3]), "r"(b[0]), "r"(b[1]));
}
#define CPWAIT(n)  asm volatile("cp.async.wait_group %0;" :: "n"(n) : "memory")
#define CPCOMMIT() asm volatile("cp.async.commit_group;" ::: "memory")
__device__ __forceinline__ void barg(int id) {
    asm volatile("bar.sync %0, 256;" :: "r"(id) : "memory");
}

// Hierarchical grid barrier: 8 leaves x 16 CTAs -> root x 8 -> flag bump.
// Arrival atomics parallelize across 8 L2 addresses (~430cyc) instead of
// serializing 128-deep on one (~3.5k). Snapshot-then-poll on the flag:
// flag cannot advance past the snapshot until this CTA arrives, and is
// bumped exactly once per epoch, so poll-until-changed is exact.
__device__ __forceinline__ void grid_bar(int bj) {
    __syncthreads();
    if (threadIdx.x == 0) {
        unsigned f0;
        asm volatile("ld.acquire.gpu.u32 %0, [%1];"
                     : "=r"(f0) : "l"(&g_flag) : "memory");
        unsigned lt;
        unsigned* leaf = &g_leaf[(bj >> 4) * 64];
        asm volatile("atom.add.acq_rel.gpu.u32 %0, [%1], 1;"
                     : "=r"(lt) : "l"(leaf) : "memory");
        if ((lt & 15u) == 15u) {               // leaf complete -> arrive root
            unsigned rt;
            asm volatile("atom.add.acq_rel.gpu.u32 %0, [%1], 1;"
                         : "=r"(rt) : "l"(&g_root) : "memory");
            if ((rt & 7u) == 7u)               // root complete -> release
                asm volatile("red.add.release.gpu.u32 [%0], 1;"
                             :: "l"(&g_flag) : "memory");
        }
        unsigned cur;
        do {
            asm volatile("ld.acquire.gpu.u32 %0, [%1];"
                         : "=r"(cur) : "l"(&g_flag) : "memory");
        } while (cur == f0);
    }
    __syncthreads();
}

// 64-row pair staged by ALL 512 threads (h0)
__device__ __forceinline__ void stage_pair_all(uint32_t smb, uint32_t bufbyte,
    const __half* __restrict__ src64, int tid)
{
    #pragma unroll
    for (int j = 0; j < 8; j++) {
        int u = tid + j * 512;
        int b = u >> 6, seg = u & 63;
        cp16s(smb + bufbyte
                  + (uint32_t)((b >> 5) * (int)CHUNKB + (b & 31) * 1040 + seg * 16),
              src64 + (size_t)b * 512 + seg * 8);
    }
    CPCOMMIT();
}
// 64-row pair staged by one 256-thread group (x, h1)
__device__ __forceinline__ void stage_pair_grp(uint32_t smb, uint32_t bufbyte,
    const __half* __restrict__ src64, int gtid)
{
    #pragma unroll
    for (int j = 0; j < 16; j++) {
        int u = gtid + j * 256;
        int b = u >> 6, seg = u & 63;
        cp16s(smb + bufbyte
                  + (uint32_t)((b >> 5) * (int)CHUNKB + (b & 31) * 1040 + seg * 16),
              src64 + (size_t)b * 512 + seg * 8);
    }
    CPCOMMIT();
}

// single-term: 8 ldsm + 16 mma per chunk (64k-window per warp)
__device__ __forceinline__ void chunk_mma1(uint32_t smb, uint32_t bufo, int half_,
    const uint32_t wfm[4][4], uint32_t blane, int myks, float d[8][4])
{
    #pragma unroll
    for (int pair = 0; pair < 2; pair++) {
        #pragma unroll
        for (int kb = 0; kb < 4; kb++) {
            uint32_t addr = smb + bufo + (uint32_t)(pair * 16640) + blane
                          + (uint32_t)(myks * 128 + kb * 32);
            uint32_t b4[4];
            ldsm_x4(addr, b4);
            int nt = half_ * 4 + pair * 2;
            mma16816(d[nt],     wfm[kb], b4);
            mma16816(d[nt + 1], wfm[kb], b4 + 2);
        }
    }
}

__device__ __forceinline__ void store_full(float* smf, uint32_t gbF,
    int myks, int lane, const float d[8][4])
{
    float* gb0 = smf + gbF + myks * 1088 + (lane >> 2) * 68 + 2 * (lane & 3);
    #pragma unroll
    for (int nt = 0; nt < 8; nt++) {
        *(float2*)(gb0 + nt * 8)          = make_float2(d[nt][0], d[nt][1]);
        *(float2*)(gb0 + 8 * 68 + nt * 8) = make_float2(d[nt][2], d[nt][3]);
    }
}

// pairwise-tree gate sum over 8 k-slices
__device__ __forceinline__ float gate_sum(const float* q) {
    float s0 = q[0] + q[1 * 1088], s1 = q[2 * 1088] + q[3 * 1088];
    float s2 = q[4 * 1088] + q[5 * 1088], s3 = q[6 * 1088] + q[7 * 1088];
    return (s0 + s1) + (s2 + s3);
}

__global__ void convert_x(const float* __restrict__ x) {
    size_t i = (size_t)blockIdx.x * blockDim.x + threadIdx.x;   // float4 idx
    float4 v = reinterpret_cast<const float4*>(x)[i];
    __half2* p = reinterpret_cast<__half2*>(g_xh);
    p[2 * i]     = __floats2half2_rn(v.x, v.y);
    p[2 * i + 1] = __floats2half2_rn(v.z, v.w);
}

__global__ void __launch_bounds__(NTHR, 1) lstm_persistent(
    const float* __restrict__ Wxh,  // [2, 2048, 512]
    const float* __restrict__ Whh,  // [2, 2048, 512]
    const float* __restrict__ bxh,  // [2, 2048]
    const float* __restrict__ bhh,  // [2, 2048]
    float* __restrict__ out)        // [T*B*H] ++ hT[2,B,H] ++ cT[2,B,H]
{
    extern __shared__ float smf[];
    char* smc = (char*)smf;
    const uint32_t smb = (uint32_t)__cvta_generic_to_shared(smf);
    const int tid = threadIdx.x;
    const int bj  = blockIdx.x;

    const int wid = tid >> 5, lane = tid & 31, gtid = tid & 255;
    const bool isA = (wid < 8);                  // A = L1 (h0.Wx1 + h1.Wh1)
    const int myks = isA ? wid : wid - 8;        // B = L0' (x.Wx0 + h0.Wh0)

    const uint32_t wloff = (uint32_t)(((lane & 7) + ((lane >> 3) & 1) * 8) * 1040
                                     + ((lane >> 4) & 1) * 16);
    const uint32_t blane = (uint32_t)((((lane >> 4) & 1) * 8 + (lane & 7)) * 1040
                                     + ((lane >> 3) & 1) * 16);

    // A: [0]=Wx1 [1]=Wh1 ; B: [0]=Wx0 [1]=Wh0   (single-term fp16)
    uint32_t wf[2][4][4];

    // ---- prologue: weights -> fp16 tiles -> reg frags ----
    for (int l = 0; l < 2; l++) {
        for (int idx = tid; idx < 16384; idx += NTHR) {
            int m = idx >> 13, rem = idx & 8191, c = rem >> 9, k = rem & 511;
            const float* bp = m ? Whh : Wxh;
            float w = bp[((size_t)l * 2048 + (size_t)(c >> 2) * 512
                        + bj * 4 + (c & 3)) * 512 + k];
            *(__half*)(smc + m * 16640 + c * 1040 + k * 2) = __float2half(w);
        }
        __syncthreads();
        if ((l == 1) == isA) {
            #pragma unroll
            for (int kb = 0; kb < 4; kb++) {
                uint32_t ko = wloff + (uint32_t)((myks * 64 + kb * 16) * 2);
                ldsm_x4(smb + 0u * 16640u + ko, wf[0][kb]);   // Wx{l}
                ldsm_x4(smb + 1u * 16640u + ko, wf[1][kb]);   // Wh{l}
            }
        }
        __syncthreads();
    }
    if (tid < 32) {
        int l = tid >> 4, j = tid & 15;
        int n = (j >> 2) * 512 + bj * 4 + (j & 3);
        smf[BSF + tid] = bxh[l * 2048 + n] + bhh[l * 2048 + n];
    }
    if (tid < 256)   // zero h1 slot 2 (h1(-1), read at t=0)
        g_h1h[2][bj * 256 + tid] = __float2half(0.f);

    const int ub = gtid >> 2, ucc = tid & 3;
    const int col = bj * 4 + ucc;
    const int hidx = ub * HID + col;
    float c0r = 0.f, c1r = 0.f, h0last = 0.f, h1last = 0.f;
    float d[8][4];

    #pragma unroll
    for (int nt = 0; nt < 8; nt++)
        d[nt][0] = d[nt][1] = d[nt][2] = d[nt][3] = 0.f;

    // ---- bootstrap: h0(0) = f(x(0).Wx0 + b0), h(-1)=0 ----
    if (!isA) {
        stage_pair_grp(smb, XB0, g_xh, gtid);
        CPWAIT(0); barg(2);
        chunk_mma1(smb, XB0, 0, wf[0], blane, myks, d);
        chunk_mma1(smb, XB1, 1, wf[0], blane, myks, d);
        barg(2);                         // all B x-reads done (GB0 aliases x)
        store_full(smf, GB0F, myks, lane, d);
        barg(2);
        float gate[4];
        #pragma unroll
        for (int g = 0; g < 4; g++)
            gate[g] = gate_sum(smf + GB0F + (g * 4 + ucc) * 68 + ub)
                    + smf[BSF + g * 4 + ucc];
        float ig = fsigm(gate[0]), fg = fsigm(gate[1]);
        float gg = ftanh(gate[2]), og = fsigm(gate[3]);
        c0r = ig * gg;
        h0last = og * ftanh(c0r);
        g_h0h[0][hidx] = __float2half(h0last);
    }
    grid_bar(bj);

    // ---- main loop: interval t => L1(t) (A) + L0(t+1) (B) ----
    for (int t = 0; t < T_LEN; t++) {
        const int s_h0r = t % 3, s_h1r = (t + 2) % 3;
        const int s_h0w = (t + 1) % 3, s_h1w = t % 3;
        const size_t xo1 = (size_t)((t + 1 < T_LEN) ? t + 1 : T_LEN - 1)
                         * (BSZ * HID);

        #pragma unroll
        for (int nt = 0; nt < 8; nt++)
            d[nt][0] = d[nt][1] = d[nt][2] = d[nt][3] = 0.f;

        // staging. Commit order per thread: A = [h0, h1], B = [x, h0].
        if (!isA) stage_pair_grp(smb, XB0, g_xh + xo1, gtid);
        stage_pair_all(smb, HB(0), g_h0h[s_h0r], tid);
        if (isA)  stage_pair_grp(smb, H1P, g_h1h[s_h1r], gtid);

        if (isA) {
            CPWAIT(1);                         // own h0 part done (h1 pending)
        } else {
            CPWAIT(1);                         // x done (h0 pending)
            barg(2);
            chunk_mma1(smb, XB0, 0, wf[0], blane, myks, d);   // x_0 . Wx0
            chunk_mma1(smb, XB1, 1, wf[0], blane, myks, d);   // x_1 . Wx0
            CPWAIT(0);                         // own h0 part done
        }
        __syncthreads();                       // h0 rendezvous (joint)

        if (isA) {
            chunk_mma1(smb, HB(0), 0, wf[0], blane, myks, d); // h0_0 . Wx1
            chunk_mma1(smb, HB(1), 1, wf[0], blane, myks, d); // h0_1 . Wx1
            CPWAIT(0); barg(1);                // h1 pair landed (A-staged)
            chunk_mma1(smb, H1P,            0, wf[1], blane, myks, d); // h1_0.Wh1
            chunk_mma1(smb, H1P + CHUNKB,   1, wf[1], blane, myks, d); // h1_1.Wh1
            store_full(smf, GB1F, myks, lane, d);
            barg(1);                           // group-local epilogue sync
            // ---- A update: h1(t) ----
            float gate[4];
            #pragma unroll
            for (int g = 0; g < 4; g++)
                gate[g] = gate_sum(smf + GB1F + (g * 4 + ucc) * 68 + ub)
                        + smf[BSF + 16 + g * 4 + ucc];
            float ig = fsigm(gate[0]), fg = fsigm(gate[1]);
            float gg = ftanh(gate[2]), og = fsigm(gate[3]);
            c1r = fg * c1r + ig * gg;
            h1last = og * ftanh(c1r);
            g_h1h[s_h1w][hidx] = __float2half(h1last);
            out[(size_t)t * (BSZ * HID) + hidx] = h1last;
        } else {
            chunk_mma1(smb, HB(0), 0, wf[1], blane, myks, d); // h0_0 . Wh0
            chunk_mma1(smb, HB(1), 1, wf[1], blane, myks, d); // h0_1 . Wh0
            store_full(smf, GB0F, myks, lane, d);
            barg(2);                           // group-local epilogue sync
            // ---- B update: h0(t+1) ----
            if (t < T_LEN - 1) {
                float gate[4];
                #pragma unroll
                for (int g = 0; g < 4; g++)
                    gate[g] = gate_sum(smf + GB0F + (g * 4 + ucc) * 68 + ub)
                            + smf[BSF + g * 4 + ucc];
                float ig = fsigm(gate[0]), fg = fsigm(gate[1]);
                float gg = ftanh(gate[2]), og = fsigm(gate[3]);
                c0r = fg * c0r + ig * gg;
                h0last = og * ftanh(c0r);
                g_h0h[s_h0w][hidx] = __float2half(h0last);
            }
        }
        grid_bar(bj);
    }
    CPWAIT(0);

    // ---- epilogue: each group owns its states ----
    {
        const size_t OFF = (size_t)T_LEN * BSZ * HID;
        if (!isA) {
            out[OFF +         hidx] = h0last;    // hT layer 0
            out[OFF + 65536 + hidx] = c0r;       // cT layer 0
        } else {
            out[OFF + 32768 + hidx] = h1last;    // hT layer 1
            out[OFF + 98304 + hidx] = c1r;       // cT layer 1
        }
    }
}

extern "C" void kernel_launch(void* const* d_in, const int* in_sizes, int n_in,
                              void* d_out, int out_size) {
    const float* x   = (const float*)d_in[0];
    const float* Wxh = (const float*)d_in[1];
    const float* Whh = (const float*)d_in[2];
    const float* bxh = (const float*)d_in[3];
    const float* bhh = (const float*)d_in[4];
    float* out = (float*)d_out;

    convert_x<<<(T_LEN * BSZ * HID / 4) / 256, 256>>>(x);

    cudaFuncSetAttribute(lstm_persistent,
                         cudaFuncAttributeMaxDynamicSharedMemorySize, SMEM_BYTES);
    lstm_persistent<<<NCTA, NTHR, SMEM_BYTES>>>(Wxh, Whh, bxh, bhh, out);
}